// round 3
// baseline (speedup 1.0000x reference)
#include <cuda_runtime.h>
#include <cuda_bf16.h>
#include <mma.h>
#include <cstdint>

using namespace nvcuda;

// Problem constants
#define BB   8
#define DD   512
#define KK   32
#define NN   16384      // 128*128
#define TN   32         // n per subtile (halved: enables double buffering)
#define CHUNK 1024      // n per CTA
#define NSUB (CHUNK/TN) // 32

// SMEM pitches (floats), multiples of 4 (wmma ldm requirement)
#define XS_LD 36
#define CS_LD 516
#define AS_LD 36
#define ES_LD 516

// SMEM float counts
#define XS_F (DD*XS_LD)     // 18432 per buffer
#define CS_F (KK*CS_LD)     // 16512
#define AS_F (TN*AS_LD)     // 1152 (x2 partial buffers)
#define X2_F (32*TN)        // 1024
#define SMEM_FLOATS (2*XS_F + CS_F + 2*AS_F + X2_F + 32 + 32 + 32)
#define SMEM_BYTES (SMEM_FLOATS * 4)   // 227,584 B total -> fits 232448 cap

__device__ __forceinline__ void cp_async16(void* smem_dst, const void* gmem_src) {
    uint32_t s = (uint32_t)__cvta_generic_to_shared(smem_dst);
    asm volatile("cp.async.cg.shared.global [%0], [%1], 16;\n" :: "r"(s), "l"(gmem_src));
}
template<int N>
__device__ __forceinline__ void cp_async_wait() {
    asm volatile("cp.async.wait_group %0;\n" :: "n"(N) : "memory");
}

// stage X[0:512][n0:n0+32] -> dst (8 x 16B per thread), one commit group
__device__ __forceinline__ void stage_tile(const float* __restrict__ Xb, float* dst,
                                           int n0, int t) {
    const int j  = t & 7;    // n-quad
    const int dr = t >> 3;   // 64 d-rows per pass
    const float* src = Xb + n0 + j * 4;
    #pragma unroll
    for (int r = 0; r < 8; ++r) {
        int d = r * 64 + dr;
        cp_async16(&dst[d * XS_LD + j * 4], src + (size_t)d * NN);
    }
    asm volatile("cp.async.commit_group;\n" ::: "memory");
}

__global__ __launch_bounds__(512, 1)
void encoding_kernel(const float* __restrict__ X,
                     const float* __restrict__ CW,
                     const float* __restrict__ scale,
                     float* __restrict__ out)
{
    extern __shared__ float sm[];
    float* Xs0 = sm;                 // [512][36] X tile buffer 0
    float* Xs1 = Xs0 + XS_F;         // [512][36] X tile buffer 1
    float* Cs  = Xs1 + XS_F;         // [32][516] codewords, pre-rounded tf32
    float* As  = Cs + CS_F;          // [32][36]  GEMM1 partial (d-half 0), then A
    float* As2 = As + AS_F;          // [32][36]  GEMM1 partial (d-half 1)
    float* x2p = As2 + AS_F;         // [32][32]  x^2 partials
    float* Ssm = x2p + X2_F;         // [32]
    float* c2s = Ssm + 32;           // [32]
    float* scs = c2s + 32;           // [32]

    const int t = threadIdx.x;
    const int w = t >> 5;
    const int b = blockIdx.y;
    const int nbase = blockIdx.x * CHUNK;
    const float* Xb = X + (size_t)b * DD * NN;

    // ---- one-time: codewords (RN-rounded tf32), scale, S=0, c2 ----
    for (int i = t; i < KK * DD; i += 512) {
        int k = i >> 9, d = i & 511;
        Cs[k * CS_LD + d] = wmma::__float_to_tf32(CW[i]);
    }
    if (t < 32) { Ssm[t] = 0.f; scs[t] = scale[t]; }
    __syncthreads();
    if (t < 32) {
        float s = 0.f;
        #pragma unroll 8
        for (int d = 0; d < DD; ++d) { float v = Cs[t * CS_LD + d]; s += v * v; }
        c2s[t] = s;   // consumed only after later barriers
    }

    // ---- persistent GEMM2 accumulators: warp w owns d in [w*32, w*32+32) ----
    wmma::fragment<wmma::accumulator, 16, 16, 8, float> eacc[2][2];
    #pragma unroll
    for (int kc = 0; kc < 2; ++kc)
        #pragma unroll
        for (int dt = 0; dt < 2; ++dt)
            wmma::fill_fragment(eacc[kc][dt], 0.f);

    // ---- pipeline prologue: tiles 0 and 1 in flight ----
    stage_tile(Xb, Xs0, nbase + 0 * TN, t);
    stage_tile(Xb, Xs1, nbase + 1 * TN, t);

    for (int s = 0; s < NSUB; ++s) {
        // wait for tile s (keep at most one younger group in flight)
        if (s + 1 < NSUB) cp_async_wait<1>(); else cp_async_wait<0>();
        __syncthreads();

        float* Xt = (s & 1) ? Xs1 : Xs0;

        if (w < 8) {
            // ---- GEMM1 (warps 0-7): P[n][k] partials; warp = (nc, kc, half) ----
            const int nc = w & 1, kc = (w >> 1) & 1, half = w >> 2;
            wmma::fragment<wmma::accumulator, 16, 16, 8, float> p;
            wmma::fill_fragment(p, 0.f);
            const int ds0 = half * 32;
            #pragma unroll 8
            for (int ds = ds0; ds < ds0 + 32; ++ds) {
                wmma::fragment<wmma::matrix_a, 16, 16, 8, wmma::precision::tf32, wmma::col_major> a;
                wmma::fragment<wmma::matrix_b, 16, 16, 8, wmma::precision::tf32, wmma::col_major> bf;
                wmma::load_matrix_sync(a, Xt + ds * 8 * XS_LD + nc * 16, XS_LD);
                #pragma unroll
                for (int i = 0; i < a.num_elements; ++i) a.x[i] = wmma::__float_to_tf32(a.x[i]);
                wmma::load_matrix_sync(bf, Cs + kc * 16 * CS_LD + ds * 8, CS_LD);
                wmma::mma_sync(p, a, bf, p);
            }
            float* dst = half ? As2 : As;
            wmma::store_matrix_sync(dst + nc * 16 * AS_LD + kc * 16, p, AS_LD, wmma::mem_row_major);
        } else {
            // ---- x^2 + RN tf32 conversion in place (warps 8-15), vectorized ----
            const int tt = t - 256;
            const int j  = tt & 7;     // n-quad
            const int dp = tt >> 3;    // 32 partitions of 16 d-rows
            float a0 = 0.f, a1 = 0.f, a2 = 0.f, a3 = 0.f;
            #pragma unroll
            for (int r = 0; r < 16; ++r) {
                int d = dp * 16 + r;
                float4 v = *(float4*)&Xt[d * XS_LD + j * 4];
                a0 += v.x * v.x; a1 += v.y * v.y; a2 += v.z * v.z; a3 += v.w * v.w;
                v.x = wmma::__float_to_tf32(v.x);
                v.y = wmma::__float_to_tf32(v.y);
                v.z = wmma::__float_to_tf32(v.z);
                v.w = wmma::__float_to_tf32(v.w);
                *(float4*)&Xt[d * XS_LD + j * 4] = v;
            }
            x2p[dp * TN + j * 4 + 0] = a0;
            x2p[dp * TN + j * 4 + 1] = a1;
            x2p[dp * TN + j * 4 + 2] = a2;
            x2p[dp * TN + j * 4 + 3] = a3;
        }
        __syncthreads();

        // ---- softmax over k: 16 threads per pixel, 2 k each ----
        {
            const int n = t >> 4, q = t & 15, ks = q * 2;
            float x2n = x2p[(2 * q) * TN + n] + x2p[(2 * q + 1) * TN + n];
            x2n += __shfl_xor_sync(0xffffffffu, x2n, 1);
            x2n += __shfl_xor_sync(0xffffffffu, x2n, 2);
            x2n += __shfl_xor_sync(0xffffffffu, x2n, 4);
            x2n += __shfl_xor_sync(0xffffffffu, x2n, 8);
            float sl[2];
            float m = -1e30f;
            #pragma unroll
            for (int jj = 0; jj < 2; ++jj) {
                int k = ks + jj;
                float xc = As[n * AS_LD + k] + As2[n * AS_LD + k];
                float v = scs[k] * (x2n - 2.f * xc + c2s[k]);
                sl[jj] = v; m = fmaxf(m, v);
            }
            m = fmaxf(m, __shfl_xor_sync(0xffffffffu, m, 1));
            m = fmaxf(m, __shfl_xor_sync(0xffffffffu, m, 2));
            m = fmaxf(m, __shfl_xor_sync(0xffffffffu, m, 4));
            m = fmaxf(m, __shfl_xor_sync(0xffffffffu, m, 8));
            float ssum = 0.f;
            #pragma unroll
            for (int jj = 0; jj < 2; ++jj) { sl[jj] = __expf(sl[jj] - m); ssum += sl[jj]; }
            ssum += __shfl_xor_sync(0xffffffffu, ssum, 1);
            ssum += __shfl_xor_sync(0xffffffffu, ssum, 2);
            ssum += __shfl_xor_sync(0xffffffffu, ssum, 4);
            ssum += __shfl_xor_sync(0xffffffffu, ssum, 8);
            const float inv = 1.0f / ssum;
            #pragma unroll
            for (int jj = 0; jj < 2; ++jj)
                As[n * AS_LD + ks + jj] = wmma::__float_to_tf32(sl[jj] * inv);  // pre-round A
        }
        __syncthreads();

        // ---- per-CTA S_k += sum_n A[n][k] (warp 0, no barrier needed after) ----
        if (t < 32) {
            float acc = 0.f;
            #pragma unroll
            for (int n = 0; n < TN; ++n) acc += As[n * AS_LD + t];
            Ssm[t] += acc;
        }

        // ---- GEMM2 (all 16 warps): E[k][d] += sum_n A[n][k] * Xt[d][n] ----
        {
            #pragma unroll
            for (int ns = 0; ns < 4; ++ns) {
                wmma::fragment<wmma::matrix_a, 16, 16, 8, wmma::precision::tf32, wmma::col_major> a2[2];
                wmma::load_matrix_sync(a2[0], As + ns * 8 * AS_LD,      AS_LD);
                wmma::load_matrix_sync(a2[1], As + ns * 8 * AS_LD + 16, AS_LD);
                #pragma unroll
                for (int dt = 0; dt < 2; ++dt) {
                    wmma::fragment<wmma::matrix_b, 16, 16, 8, wmma::precision::tf32, wmma::col_major> b2;
                    wmma::load_matrix_sync(b2, Xt + (w * 32 + dt * 16) * XS_LD + ns * 8, XS_LD);
                    wmma::mma_sync(eacc[0][dt], a2[0], b2, eacc[0][dt]);
                    wmma::mma_sync(eacc[1][dt], a2[1], b2, eacc[1][dt]);
                }
            }
        }
        __syncthreads();   // all warps done with Xt -> safe to refill

        // ---- prefetch tile s+2 into the buffer just freed (overlaps next iter) ----
        if (s + 2 < NSUB)
            stage_tile(Xb, Xt, nbase + (s + 2) * TN, t);
    }

    // ---- epilogue: dump accumulators, fold -S_k*c_k, atomicAdd to out ----
    float* Es = sm;        // reuse X buffers (32 x 516 floats fits easily)
    #pragma unroll
    for (int kc = 0; kc < 2; ++kc)
        #pragma unroll
        for (int dt = 0; dt < 2; ++dt)
            wmma::store_matrix_sync(Es + kc * 16 * ES_LD + w * 32 + dt * 16,
                                    eacc[kc][dt], ES_LD, wmma::mem_row_major);
    __syncthreads();

    for (int i = t; i < KK * DD; i += 512) {
        int k = i >> 9, d = i & 511;
        float v = Es[k * ES_LD + d] - Ssm[k] * Cs[k * CS_LD + d];
        atomicAdd(&out[(size_t)b * KK * DD + i], v);
    }
}

extern "C" void kernel_launch(void* const* d_in, const int* in_sizes, int n_in,
                              void* d_out, int out_size) {
    (void)in_sizes; (void)n_in;
    const float* X     = (const float*)d_in[0];
    const float* CW    = (const float*)d_in[1];
    const float* scale = (const float*)d_in[2];
    float* out = (float*)d_out;

    cudaFuncSetAttribute(encoding_kernel,
                         cudaFuncAttributeMaxDynamicSharedMemorySize, SMEM_BYTES);

    // d_out is poisoned; atomics need zero init (graph-capturable memset node)
    cudaMemsetAsync(d_out, 0, (size_t)out_size * sizeof(float));

    dim3 grid(NN / CHUNK, BB);   // 16 x 8 = 128 CTAs
    dim3 block(512);
    encoding_kernel<<<grid, block, SMEM_BYTES>>>(X, CW, scale, out);
}

// round 5
// speedup vs baseline: 1.0427x; 1.0427x over previous
#include <cuda_runtime.h>
#include <mma.h>
#include <cstdint>

using namespace nvcuda;

#define BB 8
#define DD 512
#define KK 32
#define NN 16384

// 16 MB scratch for soft-assign matrix A[b][n][k] (tf32-rounded by K1)
__device__ float A_buf[(size_t)BB * NN * KK];

// ============================================================================
// Kernel 1: A = softmax_k( s_k * (||x||^2 - 2 x.c_k + ||c_k||^2) )
//   grid (64, 8), 512 threads. Per CTA: 256 pixels, D chunked 8 x 64.
//   Staging: LDG.128 -> x^2 accum (raw) -> RN tf32 cvt -> STS. One bar/chunk.
// ============================================================================
#define T1N  256
#define T1DC 64
#define NCH  (DD/T1DC)        // 8
#define X1LD 264              // == 8 (mod 32): conflict-free matrix_a loads
#define X1F  (T1DC*X1LD)      // 16896 floats per buffer
#define C1LD 516              // == 4 (mod 32): conflict-free matrix_b loads
#define C1F  (KK*C1LD)        // 16512
#define AS1LD 36
#define SM1_FLOATS (2*X1F + C1F + 64)
#define SM1_BYTES  (SM1_FLOATS*4)    // 201,728 B

__global__ __launch_bounds__(512, 1)
void k1_assign(const float* __restrict__ X,
               const float* __restrict__ CW,
               const float* __restrict__ scale)
{
    extern __shared__ float sm[];
    float* Xs0 = sm;                  // [64][264]
    float* Xs1 = Xs0 + X1F;           // [64][264]
    float* Cs  = Xs1 + X1F;           // [32][516] tf32-rounded codewords
    float* c2s = Cs + C1F;            // [32]
    float* scs = c2s + 32;            // [32]
    float* As  = Xs0;                 // epilogue reuse: [256][36]
    float* x2p = Xs1;                 // epilogue reuse: [8][264]

    const int t = threadIdx.x;
    const int w = t >> 5;
    const int b = blockIdx.y;
    const int n0 = blockIdx.x * T1N;
    const float* Xb = X + (size_t)b * DD * NN;

    // staging map: j = n-quad (0..63), dr = d-row within group of 8
    const int j  = t & 63;
    const int dr = t >> 6;
    const float* gsrc = Xb + (size_t)dr * NN + n0 + j * 4;

    // prefetch chunk 0 into registers (overlaps the Cs staging below)
    float4 R[8];
    #pragma unroll
    for (int r = 0; r < 8; ++r)
        R[r] = *(const float4*)(gsrc + (size_t)(r * 8) * NN);

    // codewords -> SMEM (RN tf32), scale
    for (int i = t; i < KK * DD; i += 512) {
        int k = i >> 9, d = i & 511;
        Cs[k * C1LD + d] = wmma::__float_to_tf32(CW[i]);
    }
    if (t < 32) scs[t] = scale[t];
    __syncthreads();
    if (t < 32) {
        float s = 0.f;
        #pragma unroll 8
        for (int d = 0; d < DD; ++d) { float v = Cs[t * C1LD + d]; s += v * v; }
        c2s[t] = s;    // consumed only after later barriers
    }

    // persistent GEMM1 accumulators: warp w owns n in [w*16, w*16+16), all 32 k
    wmma::fragment<wmma::accumulator, 16, 16, 8, float> p0, p1;
    wmma::fill_fragment(p0, 0.f);
    wmma::fill_fragment(p1, 0.f);
    float xa = 0.f, xb2 = 0.f, xc = 0.f, xd2 = 0.f;  // x^2 partials for n=j*4..+3

    for (int c = 0; c < NCH; ++c) {
        float* Xt = (c & 1) ? Xs1 : Xs0;

        // consume R: x^2 (raw), cvt, STS
        #pragma unroll
        for (int r = 0; r < 8; ++r) {
            float4 v = R[r];
            xa += v.x * v.x; xb2 += v.y * v.y; xc += v.z * v.z; xd2 += v.w * v.w;
            v.x = wmma::__float_to_tf32(v.x);
            v.y = wmma::__float_to_tf32(v.y);
            v.z = wmma::__float_to_tf32(v.z);
            v.w = wmma::__float_to_tf32(v.w);
            *(float4*)&Xt[(r * 8 + dr) * X1LD + j * 4] = v;
        }
        // issue LDGs for next chunk (consumed after the barrier + GEMM1)
        if (c + 1 < NCH) {
            const float* g = gsrc + (size_t)(c + 1) * T1DC * NN;
            #pragma unroll
            for (int r = 0; r < 8; ++r)
                R[r] = *(const float4*)(g + (size_t)(r * 8) * NN);
        }
        __syncthreads();

        // GEMM1 on this chunk: P[16n x 32k] += X^T C^T (fragments pre-rounded)
        #pragma unroll
        for (int ds = 0; ds < 8; ++ds) {
            wmma::fragment<wmma::matrix_a, 16, 16, 8, wmma::precision::tf32, wmma::col_major> a;
            wmma::fragment<wmma::matrix_b, 16, 16, 8, wmma::precision::tf32, wmma::col_major> b0, b1;
            wmma::load_matrix_sync(a, Xt + ds * 8 * X1LD + w * 16, X1LD);
            int dg = c * T1DC + ds * 8;
            wmma::load_matrix_sync(b0, Cs + dg, C1LD);
            wmma::load_matrix_sync(b1, Cs + 16 * C1LD + dg, C1LD);
            wmma::mma_sync(p0, a, b0, p0);
            wmma::mma_sync(p1, a, b1, p1);
        }
        // single barrier per chunk: next iter's STS into the other buffer is
        // fenced by this iter's post-GEMM position (see hazard analysis)
    }
    __syncthreads();   // all GEMM1 done; X buffers now reusable

    // publish x^2 partials: [dr][n]
    *(float4*)&x2p[dr * X1LD + j * 4] = make_float4(xa, xb2, xc, xd2);
    // dump P to As (warp-disjoint rows; safe without extra barrier)
    wmma::store_matrix_sync(As + (w * 16) * AS1LD,      p0, AS1LD, wmma::mem_row_major);
    wmma::store_matrix_sync(As + (w * 16) * AS1LD + 16, p1, AS1LD, wmma::mem_row_major);
    __syncthreads();

    // softmax: 2 threads per pixel, 16 k each; write tf32-rounded A (coalesced)
    {
        const int n = t >> 1, h = t & 1, ks = h * 16;
        float x2n = 0.f;
        #pragma unroll
        for (int r = 0; r < 8; ++r) x2n += x2p[r * X1LD + n];
        float sl[16];
        float m = -1e30f;
        #pragma unroll
        for (int jj = 0; jj < 16; ++jj) {
            int k = ks + jj;
            float v = scs[k] * (x2n - 2.f * As[n * AS1LD + k] + c2s[k]);
            sl[jj] = v; m = fmaxf(m, v);
        }
        m = fmaxf(m, __shfl_xor_sync(0xffffffffu, m, 1));
        float ssum = 0.f;
        #pragma unroll
        for (int jj = 0; jj < 16; ++jj) { sl[jj] = __expf(sl[jj] - m); ssum += sl[jj]; }
        ssum += __shfl_xor_sync(0xffffffffu, ssum, 1);
        const float inv = 1.0f / ssum;
        float4 o[4];
        #pragma unroll
        for (int jj = 0; jj < 16; ++jj)
            ((float*)o)[jj] = wmma::__float_to_tf32(sl[jj] * inv);
        float4* dst = (float4*)&A_buf[((size_t)b * NN + n0 + n) * KK + ks];
        dst[0] = o[0]; dst[1] = o[1]; dst[2] = o[2]; dst[3] = o[3];
    }
}

// ============================================================================
// Kernel 2: E[b,k,d] = sum_n A[b,n,k] * X[b,d,n]  -  S_k * c[k,d]
//   grid (16, 8), 512 threads. Per CTA: 1024 pixels in 32 subtiles of 32.
//   Staging: LDG.128 -> cvt(X) -> STS ; S_k accumulated in staging registers.
// ============================================================================
#define T2N    32
#define CHUNK2 1024
#define NSUB2  (CHUNK2/T2N)   // 32
#define X2LD 36               // == 4 (mod 32): conflict-free matrix_b loads
#define X2F  (DD*X2LD)        // 18432
#define A2LD 40               // == 8 (mod 32): conflict-free matrix_a loads
#define A2F  (T2N*A2LD)       // 1280
#define ES2LD 516
#define SM2_FLOATS (2*X2F + 2*A2F + 32)
#define SM2_BYTES  (SM2_FLOATS*4)     // 157,952 B

__global__ __launch_bounds__(512, 1)
void k2_aggregate(const float* __restrict__ X,
                  const float* __restrict__ CW,
                  float* __restrict__ out)
{
    extern __shared__ float sm[];
    float* Xs0 = sm;                // [512][36]
    float* Xs1 = Xs0 + X2F;
    float* As0 = Xs1 + X2F;         // [32][40]
    float* As1 = As0 + A2F;
    float* Ssm = As1 + A2F;         // [32]
    float* Es  = sm;                // epilogue reuse: [32][516]

    const int t = threadIdx.x;
    const int w = t >> 5;
    const int lane = t & 31;
    const int b = blockIdx.y;
    const int nbase = blockIdx.x * CHUNK2;
    const float* Xb = X + (size_t)b * DD * NN;
    const float* Ab = A_buf + (size_t)b * NN * KK;

    // X staging map: jx = n-quad (0..7), dx = d-row in group of 64
    const int jx = t & 7;
    const int dx = t >> 3;
    const float* gx = Xb + (size_t)dx * NN + nbase + jx * 4;
    // A staging map (t < 256): na = row, ja = k-quad
    const int na = t >> 3;
    const int ja = t & 7;

    if (t < 32) Ssm[t] = 0.f;

    // prefetch subtile 0
    float4 R[8];
    #pragma unroll
    for (int r = 0; r < 8; ++r)
        R[r] = *(const float4*)(gx + (size_t)(r * 64) * NN);
    float4 RA = make_float4(0.f, 0.f, 0.f, 0.f);
    if (t < 256) RA = *(const float4*)(Ab + (size_t)(nbase + na) * KK + ja * 4);

    // persistent accumulators: warp w owns d in [w*32, w*32+32), all 32 k
    wmma::fragment<wmma::accumulator, 16, 16, 8, float> eacc[2][2];
    #pragma unroll
    for (int kc = 0; kc < 2; ++kc)
        #pragma unroll
        for (int dt = 0; dt < 2; ++dt)
            wmma::fill_fragment(eacc[kc][dt], 0.f);

    float4 sacc = make_float4(0.f, 0.f, 0.f, 0.f);  // S_k partials (k=ja*4..+3)

    for (int s = 0; s < NSUB2; ++s) {
        float* Xt = (s & 1) ? Xs1 : Xs0;
        float* At = (s & 1) ? As1 : As0;

        // consume registers: cvt X, STS both; accumulate S from A regs
        #pragma unroll
        for (int r = 0; r < 8; ++r) {
            float4 v = R[r];
            v.x = wmma::__float_to_tf32(v.x);
            v.y = wmma::__float_to_tf32(v.y);
            v.z = wmma::__float_to_tf32(v.z);
            v.w = wmma::__float_to_tf32(v.w);
            *(float4*)&Xt[(r * 64 + dx) * X2LD + jx * 4] = v;
        }
        if (t < 256) {
            *(float4*)&At[na * A2LD + ja * 4] = RA;   // A already tf32 from K1
            sacc.x += RA.x; sacc.y += RA.y; sacc.z += RA.z; sacc.w += RA.w;
        }
        // issue LDGs for next subtile
        if (s + 1 < NSUB2) {
            const int n1 = (s + 1) * T2N;
            const float* g = gx + n1;
            #pragma unroll
            for (int r = 0; r < 8; ++r)
                R[r] = *(const float4*)(g + (size_t)(r * 64) * NN);
            if (t < 256)
                RA = *(const float4*)(Ab + (size_t)(nbase + n1 + na) * KK + ja * 4);
        }
        __syncthreads();

        // GEMM2: E[k][d] += sum_n A[n][k] * X[d][n]   (no cvt anywhere)
        #pragma unroll
        for (int ns = 0; ns < 4; ++ns) {
            wmma::fragment<wmma::matrix_a, 16, 16, 8, wmma::precision::tf32, wmma::col_major> a2[2];
            wmma::load_matrix_sync(a2[0], At + ns * 8 * A2LD,      A2LD);
            wmma::load_matrix_sync(a2[1], At + ns * 8 * A2LD + 16, A2LD);
            #pragma unroll
            for (int dt = 0; dt < 2; ++dt) {
                wmma::fragment<wmma::matrix_b, 16, 16, 8, wmma::precision::tf32, wmma::col_major> b2;
                wmma::load_matrix_sync(b2, Xt + (w * 32 + dt * 16) * X2LD + ns * 8, X2LD);
                wmma::mma_sync(eacc[0][dt], a2[0], b2, eacc[0][dt]);
                wmma::mma_sync(eacc[1][dt], a2[1], b2, eacc[1][dt]);
            }
        }
        // single barrier per subtile (hazard-safe: see K1 comment)
    }
    __syncthreads();

    // fold S partials: reduce over n-groups within warp (lanes with same ja)
    if (t < 256) {
        sacc.x += __shfl_xor_sync(0xffffffffu, sacc.x, 8);
        sacc.y += __shfl_xor_sync(0xffffffffu, sacc.y, 8);
        sacc.z += __shfl_xor_sync(0xffffffffu, sacc.z, 8);
        sacc.w += __shfl_xor_sync(0xffffffffu, sacc.w, 8);
        sacc.x += __shfl_xor_sync(0xffffffffu, sacc.x, 16);
        sacc.y += __shfl_xor_sync(0xffffffffu, sacc.y, 16);
        sacc.z += __shfl_xor_sync(0xffffffffu, sacc.z, 16);
        sacc.w += __shfl_xor_sync(0xffffffffu, sacc.w, 16);
        if (lane < 8) {
            atomicAdd(&Ssm[ja * 4 + 0], sacc.x);
            atomicAdd(&Ssm[ja * 4 + 1], sacc.y);
            atomicAdd(&Ssm[ja * 4 + 2], sacc.z);
            atomicAdd(&Ssm[ja * 4 + 3], sacc.w);
        }
    }
    // dump accumulators into Es (overlaps Xs0; all reads of Xs0 are done)
    #pragma unroll
    for (int kc = 0; kc < 2; ++kc)
        #pragma unroll
        for (int dt = 0; dt < 2; ++dt)
            wmma::store_matrix_sync(Es + kc * 16 * ES2LD + w * 32 + dt * 16,
                                    eacc[kc][dt], ES2LD, wmma::mem_row_major);
    __syncthreads();

    for (int i = t; i < KK * DD; i += 512) {
        int k = i >> 9, d = i & 511;
        float v = Es[k * ES2LD + d] - Ssm[k] * CW[i];   // exact c in correction
        atomicAdd(&out[(size_t)b * KK * DD + i], v);
    }
}

// ============================================================================
extern "C" void kernel_launch(void* const* d_in, const int* in_sizes, int n_in,
                              void* d_out, int out_size) {
    (void)in_sizes; (void)n_in;
    const float* X     = (const float*)d_in[0];
    const float* CW    = (const float*)d_in[1];
    const float* scale = (const float*)d_in[2];
    float* out = (float*)d_out;

    cudaFuncSetAttribute(k1_assign,    cudaFuncAttributeMaxDynamicSharedMemorySize, SM1_BYTES);
    cudaFuncSetAttribute(k2_aggregate, cudaFuncAttributeMaxDynamicSharedMemorySize, SM2_BYTES);

    cudaMemsetAsync(d_out, 0, (size_t)out_size * sizeof(float));

    dim3 g1(NN / T1N, BB);      // 64 x 8 = 512 CTAs
    k1_assign<<<g1, 512, SM1_BYTES>>>(X, CW, scale);

    dim3 g2(NN / CHUNK2, BB);   // 16 x 8 = 128 CTAs
    k2_aggregate<<<g2, 512, SM2_BYTES>>>(X, CW, out);
}

// round 7
// speedup vs baseline: 1.2055x; 1.1561x over previous
#include <cuda_runtime.h>
#include <mma.h>
#include <cstdint>

using namespace nvcuda;

#define BB 8
#define DD 512
#define KK 32
#define NN 16384

// 16 MB scratch for soft-assign matrix A[b][n][k] (tf32-rounded by K1)
__device__ float A_buf[(size_t)BB * NN * KK];

// ============================================================================
// Kernel 1: A = softmax_k( s_k * (||x||^2 - 2 x.c_k + ||c_k||^2) )
//   grid (16, 8), 512 threads, persistent: 4 tiles of 256 pixels per CTA.
//   Per tile: D chunked 8 x 64; staging LDG.128 -> x^2 -> RN tf32 -> STS.
//   GEMM1 warp tile: 32n x 32k over a 32-d half (partials summed in softmax).
// ============================================================================
#define T1N   256
#define T1DC  64
#define NCH   (DD/T1DC)       // 8
#define TILES 4
#define X1LD 264              // == 8 (mod 32)
#define X1F  (T1DC*X1LD)      // 16896 floats per buffer
#define C1LD 516              // == 4 (mod 32)
#define C1F  (KK*C1LD)        // 16512
#define AS1LD 36
#define SM1_FLOATS (2*X1F + C1F + 64)
#define SM1_BYTES  (SM1_FLOATS*4)    // 201,472 B

__global__ __launch_bounds__(512, 1)
void k1_assign(const float* __restrict__ X,
               const float* __restrict__ CW,
               const float* __restrict__ scale)
{
    extern __shared__ float sm[];
    float* Xs0 = sm;                  // [64][264]
    float* Xs1 = Xs0 + X1F;           // [64][264]
    float* Cs  = Xs1 + X1F;           // [32][516] tf32-rounded codewords
    float* c2s = Cs + C1F;            // [32]
    float* scs = c2s + 32;            // [32]
    float* As  = Xs0;                 // epilogue: P partial half 0  [256][36]
    float* As2 = Xs1;                 // epilogue: P partial half 1  [256][36]
    float* x2p = Xs1 + 9216;          // epilogue: x^2 partials [8][X1LD]

    const int t = threadIdx.x;
    const int w = t >> 5;
    const int b = blockIdx.y;
    const int tile_base = blockIdx.x * TILES;
    const float* Xb = X + (size_t)b * DD * NN;

    // staging map: j = n-quad (0..63), dr = d-row within group of 8
    const int j  = t & 63;
    const int dr = t >> 6;

    // GEMM1 warp role: nc = 32-pixel group (0..7), half = d-half (0..1)
    const int nc = w & 7, half = w >> 3;

    // prefetch (tile 0, chunk 0) into registers
    float4 R[8];
    {
        const float* g = Xb + (size_t)dr * NN + tile_base * T1N + j * 4;
        #pragma unroll
        for (int r = 0; r < 8; ++r)
            R[r] = *(const float4*)(g + (size_t)(r * 8) * NN);
    }

    // one-time: codewords -> SMEM (RN tf32), scale, c2
    for (int i = t; i < KK * DD; i += 512) {
        int k = i >> 9, d = i & 511;
        Cs[k * C1LD + d] = wmma::__float_to_tf32(CW[i]);
    }
    if (t < 32) scs[t] = scale[t];
    __syncthreads();
    if (t < 32) {
        float s = 0.f;
        #pragma unroll 8
        for (int d = 0; d < DD; ++d) { float v = Cs[t * C1LD + d]; s += v * v; }
        c2s[t] = s;    // consumed only after later barriers
    }

    // per-tile accumulators
    wmma::fragment<wmma::accumulator, 16, 16, 8, float> p00, p01, p10, p11;
    wmma::fill_fragment(p00, 0.f); wmma::fill_fragment(p01, 0.f);
    wmma::fill_fragment(p10, 0.f); wmma::fill_fragment(p11, 0.f);
    float xa = 0.f, xb2 = 0.f, xc = 0.f, xd2 = 0.f;

    for (int u = 0; u < TILES * NCH; ++u) {
        const int c = u & 7;
        float* Xt = (u & 1) ? Xs1 : Xs0;

        // consume R: x^2 (raw), cvt, STS
        #pragma unroll
        for (int r = 0; r < 8; ++r) {
            float4 v = R[r];
            xa += v.x * v.x; xb2 += v.y * v.y; xc += v.z * v.z; xd2 += v.w * v.w;
            v.x = wmma::__float_to_tf32(v.x);
            v.y = wmma::__float_to_tf32(v.y);
            v.z = wmma::__float_to_tf32(v.z);
            v.w = wmma::__float_to_tf32(v.w);
            *(float4*)&Xt[(r * 8 + dr) * X1LD + j * 4] = v;
        }
        // prefetch next unit (next chunk, or next tile's chunk 0)
        if (u + 1 < TILES * NCH) {
            const int un = u + 1, tn = un >> 3, cn = un & 7;
            const float* g = Xb + (size_t)(cn * T1DC + dr) * NN
                           + (size_t)(tile_base + tn) * T1N + j * 4;
            #pragma unroll
            for (int r = 0; r < 8; ++r)
                R[r] = *(const float4*)(g + (size_t)(r * 8) * NN);
        }
        __syncthreads();

        // GEMM1: warp covers 32 pixels x 32 k over its 32-d half of this chunk
        #pragma unroll
        for (int ds4 = 0; ds4 < 4; ++ds4) {
            const int dl = half * 32 + ds4 * 8;        // d offset within chunk
            const int dg = c * T1DC + dl;              // global d (for Cs)
            wmma::fragment<wmma::matrix_a, 16, 16, 8, wmma::precision::tf32, wmma::col_major> a0, a1;
            wmma::fragment<wmma::matrix_b, 16, 16, 8, wmma::precision::tf32, wmma::col_major> b0, b1;
            wmma::load_matrix_sync(a0, Xt + dl * X1LD + nc * 32,      X1LD);
            wmma::load_matrix_sync(a1, Xt + dl * X1LD + nc * 32 + 16, X1LD);
            wmma::load_matrix_sync(b0, Cs + dg,              C1LD);
            wmma::load_matrix_sync(b1, Cs + 16 * C1LD + dg,  C1LD);
            wmma::mma_sync(p00, a0, b0, p00);
            wmma::mma_sync(p01, a0, b1, p01);
            wmma::mma_sync(p10, a1, b0, p10);
            wmma::mma_sync(p11, a1, b1, p11);
        }

        if (c == NCH - 1) {
            const int tile = u >> 3;
            const int n0 = (tile_base + tile) * T1N;
            __syncthreads();   // all GEMM1 reads of Xs0/Xs1 done

            // publish x^2 partials and P partials into the (now free) X buffers
            *(float4*)&x2p[dr * X1LD + j * 4] = make_float4(xa, xb2, xc, xd2);
            float* dst = half ? As2 : As;
            wmma::store_matrix_sync(dst + (nc * 32) * AS1LD,           p00, AS1LD, wmma::mem_row_major);
            wmma::store_matrix_sync(dst + (nc * 32) * AS1LD + 16,      p01, AS1LD, wmma::mem_row_major);
            wmma::store_matrix_sync(dst + (nc * 32 + 16) * AS1LD,      p10, AS1LD, wmma::mem_row_major);
            wmma::store_matrix_sync(dst + (nc * 32 + 16) * AS1LD + 16, p11, AS1LD, wmma::mem_row_major);
            __syncthreads();

            // softmax: 2 threads per pixel, 16 k each; write tf32 A (coalesced)
            {
                const int n = t >> 1, h = t & 1, ks = h * 16;
                float x2n = 0.f;
                #pragma unroll
                for (int r = 0; r < 8; ++r) x2n += x2p[r * X1LD + n];
                float sl[16];
                float m = -1e30f;
                #pragma unroll
                for (int jj = 0; jj < 16; ++jj) {
                    int k = ks + jj;
                    float xck = As[n * AS1LD + k] + As2[n * AS1LD + k];
                    float v = scs[k] * (x2n - 2.f * xck + c2s[k]);
                    sl[jj] = v; m = fmaxf(m, v);
                }
                m = fmaxf(m, __shfl_xor_sync(0xffffffffu, m, 1));
                float ssum = 0.f;
                #pragma unroll
                for (int jj = 0; jj < 16; ++jj) { sl[jj] = __expf(sl[jj] - m); ssum += sl[jj]; }
                ssum += __shfl_xor_sync(0xffffffffu, ssum, 1);
                const float inv = 1.0f / ssum;
                float4 o[4];
                #pragma unroll
                for (int jj = 0; jj < 16; ++jj)
                    ((float*)o)[jj] = wmma::__float_to_tf32(sl[jj] * inv);
                float4* dstA = (float4*)&A_buf[((size_t)b * NN + n0 + n) * KK + ks];
                dstA[0] = o[0]; dstA[1] = o[1]; dstA[2] = o[2]; dstA[3] = o[3];
            }
            __syncthreads();   // As/As2/x2p free before next tile's staging

            // reset per-tile accumulators
            wmma::fill_fragment(p00, 0.f); wmma::fill_fragment(p01, 0.f);
            wmma::fill_fragment(p10, 0.f); wmma::fill_fragment(p11, 0.f);
            xa = xb2 = xc = xd2 = 0.f;
        }
    }
}

// ============================================================================
// Kernel 2: E[b,k,d] = sum_n A[b,n,k] * X[b,d,n]  -  S_k * c[k,d]
//   grid (16, 8, 2) d-halves, 256 threads, 2 CTAs/SM.
//   Staging: LDG.128 -> cvt(X) -> STS ; S_k accumulated in staging registers.
// ============================================================================
#define T2N    32
#define CHUNK2 1024
#define NSUB2  (CHUNK2/T2N)   // 32
#define DHALF  256
#define X2LD 36               // == 4 (mod 32)
#define X2F  (DHALF*X2LD)     // 9216
#define A2LD 40               // == 8 (mod 32)
#define A2F  (T2N*A2LD)       // 1280
#define ES2LD 260
#define SM2_FLOATS (2*X2F + 2*A2F + 32)
#define SM2_BYTES  (SM2_FLOATS*4)     // 84,096 B -> 2 CTAs/SM

__global__ __launch_bounds__(256, 2)
void k2_aggregate(const float* __restrict__ X,
                  const float* __restrict__ CW,
                  float* __restrict__ out)
{
    extern __shared__ float sm[];
    float* Xs0 = sm;                // [256][36]
    float* Xs1 = Xs0 + X2F;
    float* As0 = Xs1 + X2F;         // [32][40]
    float* As1 = As0 + A2F;
    float* Ssm = As1 + A2F;         // [32]
    float* Es  = sm;                // epilogue reuse: [32][260]

    const int t = threadIdx.x;
    const int w = t >> 5;           // 0..7
    const int lane = t & 31;
    const int b = blockIdx.y;
    const int z = blockIdx.z;       // d-half
    const int nbase = blockIdx.x * CHUNK2;
    const float* Xb = X + (size_t)b * DD * NN + (size_t)z * DHALF * NN;
    const float* Ab = A_buf + (size_t)b * NN * KK;

    // X staging map: jx = n-quad (0..7), dx = d-row in group of 32
    const int jx = t & 7;
    const int dx = t >> 3;
    const float* gx = Xb + (size_t)dx * NN + nbase + jx * 4;
    // A staging map: na = row (0..31), ja = k-quad (0..7)
    const int na = t >> 3;
    const int ja = t & 7;

    if (t < 32) Ssm[t] = 0.f;

    // prefetch subtile 0
    float4 R[8];
    #pragma unroll
    for (int r = 0; r < 8; ++r)
        R[r] = *(const float4*)(gx + (size_t)(r * 32) * NN);
    float4 RA = *(const float4*)(Ab + (size_t)(nbase + na) * KK + ja * 4);

    // persistent accumulators: warp w owns local d in [w*32, w*32+32), all 32 k
    wmma::fragment<wmma::accumulator, 16, 16, 8, float> eacc[2][2];
    #pragma unroll
    for (int kc = 0; kc < 2; ++kc)
        #pragma unroll
        for (int dt = 0; dt < 2; ++dt)
            wmma::fill_fragment(eacc[kc][dt], 0.f);

    float4 sacc = make_float4(0.f, 0.f, 0.f, 0.f);  // S_k partials (k=ja*4..+3)

    for (int s = 0; s < NSUB2; ++s) {
        float* Xt = (s & 1) ? Xs1 : Xs0;
        float* At = (s & 1) ? As1 : As0;

        // consume registers: cvt X, STS both; accumulate S from A regs
        #pragma unroll
        for (int r = 0; r < 8; ++r) {
            float4 v = R[r];
            v.x = wmma::__float_to_tf32(v.x);
            v.y = wmma::__float_to_tf32(v.y);
            v.z = wmma::__float_to_tf32(v.z);
            v.w = wmma::__float_to_tf32(v.w);
            *(float4*)&Xt[(r * 32 + dx) * X2LD + jx * 4] = v;
        }
        *(float4*)&At[na * A2LD + ja * 4] = RA;   // A already tf32 from K1
        sacc.x += RA.x; sacc.y += RA.y; sacc.z += RA.z; sacc.w += RA.w;

        // issue LDGs for next subtile
        if (s + 1 < NSUB2) {
            const int n1 = (s + 1) * T2N;
            const float* g = gx + n1;
            #pragma unroll
            for (int r = 0; r < 8; ++r)
                R[r] = *(const float4*)(g + (size_t)(r * 32) * NN);
            RA = *(const float4*)(Ab + (size_t)(nbase + n1 + na) * KK + ja * 4);
        }
        __syncthreads();

        // GEMM2: E[k][d] += sum_n A[n][k] * X[d][n]
        #pragma unroll
        for (int ns = 0; ns < 4; ++ns) {
            wmma::fragment<wmma::matrix_a, 16, 16, 8, wmma::precision::tf32, wmma::col_major> a2[2];
            wmma::load_matrix_sync(a2[0], At + ns * 8 * A2LD,      A2LD);
            wmma::load_matrix_sync(a2[1], At + ns * 8 * A2LD + 16, A2LD);
            #pragma unroll
            for (int dt = 0; dt < 2; ++dt) {
                wmma::fragment<wmma::matrix_b, 16, 16, 8, wmma::precision::tf32, wmma::col_major> b2;
                wmma::load_matrix_sync(b2, Xt + (w * 32 + dt * 16) * X2LD + ns * 8, X2LD);
                wmma::mma_sync(eacc[0][dt], a2[0], b2, eacc[0][dt]);
                wmma::mma_sync(eacc[1][dt], a2[1], b2, eacc[1][dt]);
            }
        }
        // single barrier per subtile (2-buffer hazard proof as in prior rounds)
    }
    __syncthreads();

    // fold S partials across n-groups (lanes sharing ja)
    sacc.x += __shfl_xor_sync(0xffffffffu, sacc.x, 8);
    sacc.y += __shfl_xor_sync(0xffffffffu, sacc.y, 8);
    sacc.z += __shfl_xor_sync(0xffffffffu, sacc.z, 8);
    sacc.w += __shfl_xor_sync(0xffffffffu, sacc.w, 8);
    sacc.x += __shfl_xor_sync(0xffffffffu, sacc.x, 16);
    sacc.y += __shfl_xor_sync(0xffffffffu, sacc.y, 16);
    sacc.z += __shfl_xor_sync(0xffffffffu, sacc.z, 16);
    sacc.w += __shfl_xor_sync(0xffffffffu, sacc.w, 16);
    if (lane < 8) {
        atomicAdd(&Ssm[ja * 4 + 0], sacc.x);
        atomicAdd(&Ssm[ja * 4 + 1], sacc.y);
        atomicAdd(&Ssm[ja * 4 + 2], sacc.z);
        atomicAdd(&Ssm[ja * 4 + 3], sacc.w);
    }
    // dump accumulators into Es
    #pragma unroll
    for (int kc = 0; kc < 2; ++kc)
        #pragma unroll
        for (int dt = 0; dt < 2; ++dt)
            wmma::store_matrix_sync(Es + kc * 16 * ES2LD + w * 32 + dt * 16,
                                    eacc[kc][dt], ES2LD, wmma::mem_row_major);
    __syncthreads();

    for (int i = t; i < KK * DHALF; i += 256) {
        int k = i >> 8, dl = i & 255;
        int dglob = z * DHALF + dl;
        float v = Es[k * ES2LD + dl] - Ssm[k] * CW[k * DD + dglob];
        atomicAdd(&out[(size_t)b * KK * DD + k * DD + dglob], v);
    }
}

// ============================================================================
extern "C" void kernel_launch(void* const* d_in, const int* in_sizes, int n_in,
                              void* d_out, int out_size) {
    (void)in_sizes; (void)n_in;
    const float* X     = (const float*)d_in[0];
    const float* CW    = (const float*)d_in[1];
    const float* scale = (const float*)d_in[2];
    float* out = (float*)d_out;

    cudaFuncSetAttribute(k1_assign,    cudaFuncAttributeMaxDynamicSharedMemorySize, SM1_BYTES);
    cudaFuncSetAttribute(k2_aggregate, cudaFuncAttributeMaxDynamicSharedMemorySize, SM2_BYTES);

    cudaMemsetAsync(d_out, 0, (size_t)out_size * sizeof(float));

    dim3 g1(NN / (T1N * TILES), BB);   // 16 x 8 = 128 CTAs (persistent, 4 tiles)
    k1_assign<<<g1, 512, SM1_BYTES>>>(X, CW, scale);

    dim3 g2(NN / CHUNK2, BB, 2);       // 16 x 8 x 2 = 256 CTAs (2 per SM)
    k2_aggregate<<<g2, 256, SM2_BYTES>>>(X, CW, out);
}